// round 6
// baseline (speedup 1.0000x reference)
#include <cuda_runtime.h>
#include <cuda_bf16.h>
#include <math.h>

#define BB  2
#define CIN 512
#define CC  256
#define HH  48
#define WW  48
#define HWW 2304
#define LL  2304
#define DI  512
#define BL  (BB*LL)
#define BNF 0.9999950000374997f   /* 1/sqrt(1+1e-5) */

// ------------------------- static scratch (no allocs) -------------------------
__device__ __align__(256) float g_xred[BB*CC*HWW];
__device__ __align__(256) float g_p[BB*CC*HWW];
__device__ __align__(256) float g_hv[BB*CC*HWW];
__device__ __align__(256) float g_featloc[BB*CC*HWW];
__device__ __align__(256) float g_featglob[BB*CC*HWW];
__device__ __align__(256) float g_mu[BB*HWW];
__device__ __align__(256) float g_rstd[BB*HWW];
__device__ __align__(256) float g_xn[BL*CC];          // (b,l,c)
__device__ __align__(256) float g_xz[BL*2*DI];        // (b,l,1024): xm0 | z
__device__ __align__(256) float g_xm[4*BL*DI];        // (dir,b,t,d) SCAN order
__device__ __align__(256) float g_projm[4*BL*48];     // (dir,b,t,48): [dtpre16][B,C interleaved 32]
__device__ __align__(256) float4 g_dtq[4*BL*DI];      // (dt, dt*x, x, 0) SCAN order
__device__ __align__(256) __nv_bfloat16 g_y[4*BL*DI]; // SCAN order, ungated, bf16
__device__ __align__(256) float g_ysum[BL*DI];        // natural order, gated
__device__ __align__(256) float g_dtwT[16*DI];        // transposed dt_w
__device__ __align__(256) float g_xpw[48*DI];         // row-permuted xproj_w
__device__ __align__(256) int   g_map[4*LL];          // dir,t -> l
__device__ __align__(256) float g_sv[BB*CC];
__device__ __align__(256) float g_wv[BB*2*CC];

__device__ __forceinline__ int seq_map(int dir, int t) {
    if (dir == 0) return t;
    if (dir == 1) return LL - 1 - t;
    int u = (dir == 2) ? t : (LL - 1 - t);
    int h = u % HH, w = u / HH;
    return h * WW + w;
}

__device__ __forceinline__ float silu_f(float x) { return x / (1.f + __expf(-x)); }

// ------------------ one-time weight/layout prep --------------------------------
__global__ void init_misc_k(const float* __restrict__ dtw, const float* __restrict__ xpw)
{
    int i = blockIdx.x * 256 + threadIdx.x;
    if (i < 16 * DI) {                       // dt_w transpose
        int dd = i >> 4, r = i & 15;
        g_dtwT[r * DI + dd] = dtw[i];
    }
    if (i < 4 * LL) {                        // scan-order maps
        int dir = i / LL, t = i % LL;
        g_map[i] = seq_map(dir, t);
    }
    if (i < 48 * DI) {                       // xproj weight row-permutation
        int j = i >> 9, k = i & 511;
        int src = (j < 16) ? j
                : (((j - 16) & 1) ? 32 + ((j - 16) >> 1) : 16 + ((j - 16) >> 1));
        g_xpw[i] = xpw[src * DI + k];
    }
}

// ------------- 128x64 SGEMM, k16 double-buffered ------------------------------
// C[m,n]=f(sum A[m,k]B[k,n]) (TB=0, B KxN) or f(sum A[m,k]B[n,k]) (TB=1, B NxK)
// Requires M%128==0, N%64==0, K%16==0.
template<int MODE, bool TB>
__global__ void __launch_bounds__(256) gemm128(
    const float* __restrict__ A, const float* __restrict__ B, float* __restrict__ C,
    int M, int N, int K,
    long long sA, long long sB, long long sC,
    const float* __restrict__ scale, const float* __restrict__ bias,
    const float* __restrict__ extra, long long sE)
{
    __shared__ float As[2][16][132];
    __shared__ float Bs[2][16][68];
    const float* Ab = A + (long long)blockIdx.z * sA;
    const float* Bb = B + (long long)blockIdx.z * sB;
    float* Cb = C + (long long)blockIdx.z * sC;
    int tid = threadIdx.x;
    int m0 = blockIdx.y * 128, n0 = blockIdx.x * 64;
    int tx = tid & 15, ty = tid >> 4;

    int r = tid >> 1, kk = (tid & 1) * 8;
    const float* aptr = Ab + (long long)(m0 + r) * K + kk;
    int bn, bk;
    const float* bptr;
    if (TB) { bn = tid >> 2; bk = (tid & 3) * 4; bptr = Bb + (long long)(n0 + bn) * K + bk; }
    else    { bk = tid >> 4; bn = (tid & 15) * 4; bptr = Bb + (long long)bk * N + n0 + bn; }

    float pa[8], pb[4];
    {
        float4 a0 = *(const float4*)(aptr), a1 = *(const float4*)(aptr + 4);
        pa[0]=a0.x; pa[1]=a0.y; pa[2]=a0.z; pa[3]=a0.w;
        pa[4]=a1.x; pa[5]=a1.y; pa[6]=a1.z; pa[7]=a1.w;
        float4 b0 = *(const float4*)(bptr);
        pb[0]=b0.x; pb[1]=b0.y; pb[2]=b0.z; pb[3]=b0.w;
    }
#pragma unroll
    for (int e = 0; e < 8; e++) As[0][kk + e][r] = pa[e];
    if (TB) {
#pragma unroll
        for (int e = 0; e < 4; e++) Bs[0][bk + e][bn] = pb[e];
    } else {
        *(float4*)&Bs[0][bk][bn] = make_float4(pb[0], pb[1], pb[2], pb[3]);
    }
    __syncthreads();

    float acc[8][4] = {};
    int buf = 0;
    for (int k0 = 0; k0 < K; k0 += 16) {
        bool pf = (k0 + 16) < K;
        if (pf) {
            const float* an = aptr + k0 + 16;
            float4 a0 = *(const float4*)(an), a1 = *(const float4*)(an + 4);
            pa[0]=a0.x; pa[1]=a0.y; pa[2]=a0.z; pa[3]=a0.w;
            pa[4]=a1.x; pa[5]=a1.y; pa[6]=a1.z; pa[7]=a1.w;
            float4 b0;
            if (TB) b0 = *(const float4*)(bptr + k0 + 16);
            else    b0 = *(const float4*)(bptr + (long long)(k0 + 16) * N);
            pb[0]=b0.x; pb[1]=b0.y; pb[2]=b0.z; pb[3]=b0.w;
        }
#pragma unroll
        for (int k = 0; k < 16; k++) {
            float4 a0 = *(const float4*)&As[buf][k][ty*8];
            float4 a1 = *(const float4*)&As[buf][k][ty*8+4];
            float4 b4 = *(const float4*)&Bs[buf][k][tx*4];
            float a[8] = {a0.x,a0.y,a0.z,a0.w,a1.x,a1.y,a1.z,a1.w};
            float bv[4] = {b4.x,b4.y,b4.z,b4.w};
#pragma unroll
            for (int i = 0; i < 8; i++)
#pragma unroll
                for (int j = 0; j < 4; j++)
                    acc[i][j] = fmaf(a[i], bv[j], acc[i][j]);
        }
        if (pf) {
            int nb = buf ^ 1;
#pragma unroll
            for (int e = 0; e < 8; e++) As[nb][kk + e][r] = pa[e];
            if (TB) {
#pragma unroll
                for (int e = 0; e < 4; e++) Bs[nb][bk + e][bn] = pb[e];
            } else {
                *(float4*)&Bs[nb][bk][bn] = make_float4(pb[0], pb[1], pb[2], pb[3]);
            }
        }
        __syncthreads();
        buf ^= 1;
    }

#pragma unroll
    for (int i = 0; i < 8; i++) {
        int m = m0 + ty*8 + i;
        float sc = 1.f, bi = 0.f;
        if (MODE == 1) { sc = scale[m] * BNF; bi = bias[m]; }
        if (MODE == 2) { bi = bias[m]; }
        int n = n0 + tx*4;
        float v[4];
#pragma unroll
        for (int j = 0; j < 4; j++) {
            float t = acc[i][j];
            if (MODE == 1) t = fmaxf(fmaf(t, sc, bi), 0.f);
            else if (MODE == 2) t = t + bi;
            else if (MODE == 3)
                t = t * 0.25f + extra[(long long)blockIdx.z * sE + (long long)m * N + n + j];
            v[j] = t;
        }
        *(float4*)(Cb + (long long)m * N + n) = make_float4(v[0], v[1], v[2], v[3]);
    }
}

// ---------------- 128x128 SGEMM NT, k16 double-buffered -----------------------
__global__ void __launch_bounds__(256) gemm_nt_big(
    const float* __restrict__ A, const float* __restrict__ B, float* __restrict__ C,
    int M, int N, int K, long long sA, long long sC)
{
    __shared__ float As[2][16][132];
    __shared__ float Bs[2][16][132];
    int tid = threadIdx.x;
    int m0 = blockIdx.y * 128, n0 = blockIdx.x * 128;
    int r = tid >> 1, kk = (tid & 1) * 8;
    const float* aptr = A + (long long)blockIdx.z * sA + (long long)(m0 + r) * K + kk;
    const float* bptr = B + (long long)(n0 + r) * K + kk;
    int tx = tid & 15, ty = tid >> 4;

    float pa[8], pb[8];
    {
        float4 a0 = *(const float4*)(aptr), a1 = *(const float4*)(aptr + 4);
        float4 b0 = *(const float4*)(bptr), b1 = *(const float4*)(bptr + 4);
        pa[0]=a0.x; pa[1]=a0.y; pa[2]=a0.z; pa[3]=a0.w;
        pa[4]=a1.x; pa[5]=a1.y; pa[6]=a1.z; pa[7]=a1.w;
        pb[0]=b0.x; pb[1]=b0.y; pb[2]=b0.z; pb[3]=b0.w;
        pb[4]=b1.x; pb[5]=b1.y; pb[6]=b1.z; pb[7]=b1.w;
    }
#pragma unroll
    for (int e = 0; e < 8; e++) { As[0][kk+e][r] = pa[e]; Bs[0][kk+e][r] = pb[e]; }
    __syncthreads();

    float acc[8][8] = {};
    int buf = 0;
    for (int k0 = 0; k0 < K; k0 += 16) {
        bool pf = (k0 + 16) < K;
        if (pf) {
            const float* an = aptr + k0 + 16;
            const float* bn2 = bptr + k0 + 16;
            float4 a0 = *(const float4*)(an), a1 = *(const float4*)(an + 4);
            float4 b0 = *(const float4*)(bn2), b1 = *(const float4*)(bn2 + 4);
            pa[0]=a0.x; pa[1]=a0.y; pa[2]=a0.z; pa[3]=a0.w;
            pa[4]=a1.x; pa[5]=a1.y; pa[6]=a1.z; pa[7]=a1.w;
            pb[0]=b0.x; pb[1]=b0.y; pb[2]=b0.z; pb[3]=b0.w;
            pb[4]=b1.x; pb[5]=b1.y; pb[6]=b1.z; pb[7]=b1.w;
        }
#pragma unroll
        for (int k = 0; k < 16; k++) {
            float4 a0 = *(const float4*)&As[buf][k][ty*8];
            float4 a1 = *(const float4*)&As[buf][k][ty*8+4];
            float4 b0 = *(const float4*)&Bs[buf][k][tx*8];
            float4 b1 = *(const float4*)&Bs[buf][k][tx*8+4];
            float a[8] = {a0.x,a0.y,a0.z,a0.w,a1.x,a1.y,a1.z,a1.w};
            float b[8] = {b0.x,b0.y,b0.z,b0.w,b1.x,b1.y,b1.z,b1.w};
#pragma unroll
            for (int i = 0; i < 8; i++)
#pragma unroll
                for (int j = 0; j < 8; j++)
                    acc[i][j] = fmaf(a[i], b[j], acc[i][j]);
        }
        if (pf) {
            int nb = buf ^ 1;
#pragma unroll
            for (int e = 0; e < 8; e++) { As[nb][kk+e][r] = pa[e]; Bs[nb][kk+e][r] = pb[e]; }
        }
        __syncthreads();
        buf ^= 1;
    }

    float* Cb = C + (long long)blockIdx.z * sC;
#pragma unroll
    for (int i = 0; i < 8; i++) {
        int m = m0 + ty*8 + i;
        *(float4*)(Cb + (long long)m * N + n0 + tx*8)     = make_float4(acc[i][0],acc[i][1],acc[i][2],acc[i][3]);
        *(float4*)(Cb + (long long)m * N + n0 + tx*8 + 4) = make_float4(acc[i][4],acc[i][5],acc[i][6],acc[i][7]);
    }
}

// ---------------- xproj: (dir,b) x [2304 x 48] = xm @ Wperm.T -----------------
// 128x48 tile, 192 threads, 8x4 micro, k16 double-buffered.
__global__ void __launch_bounds__(192) gemm_xproj()
{
    __shared__ float As[2][16][132];
    __shared__ float Bs[2][16][52];
    int tid = threadIdx.x;
    int zb = blockIdx.y;                 // dir*BB+b
    int m0 = blockIdx.x * 128;
    const float* Ab = g_xm + (long long)zb * LL * DI;
    const float* aptr = Ab + (long long)(m0 + tid) * DI;   // valid if tid<128
    int bn = tid >> 2, bk = (tid & 3) * 4;
    const float* bptr = g_xpw + bn * DI + bk;
    int ty = tid / 12, txx = tid % 12;

    float pa[16], pb[4];
    if (tid < 128) {
#pragma unroll
        for (int j = 0; j < 4; j++) {
            float4 v = ((const float4*)aptr)[j];
            pa[j*4+0]=v.x; pa[j*4+1]=v.y; pa[j*4+2]=v.z; pa[j*4+3]=v.w;
        }
    }
    { float4 v = *(const float4*)bptr; pb[0]=v.x; pb[1]=v.y; pb[2]=v.z; pb[3]=v.w; }
    if (tid < 128) {
#pragma unroll
        for (int e = 0; e < 16; e++) As[0][e][tid] = pa[e];
    }
#pragma unroll
    for (int e = 0; e < 4; e++) Bs[0][bk + e][bn] = pb[e];
    __syncthreads();

    float acc[8][4] = {};
    int buf = 0;
    for (int k0 = 0; k0 < DI; k0 += 16) {
        bool pf = (k0 + 16) < DI;
        if (pf) {
            if (tid < 128) {
                const float* an = aptr + k0 + 16;
#pragma unroll
                for (int j = 0; j < 4; j++) {
                    float4 v = ((const float4*)an)[j];
                    pa[j*4+0]=v.x; pa[j*4+1]=v.y; pa[j*4+2]=v.z; pa[j*4+3]=v.w;
                }
            }
            float4 v = *(const float4*)(bptr + k0 + 16);
            pb[0]=v.x; pb[1]=v.y; pb[2]=v.z; pb[3]=v.w;
        }
#pragma unroll
        for (int k = 0; k < 16; k++) {
            float4 a0 = *(const float4*)&As[buf][k][ty*8];
            float4 a1 = *(const float4*)&As[buf][k][ty*8+4];
            float4 b4 = *(const float4*)&Bs[buf][k][txx*4];
            float a[8] = {a0.x,a0.y,a0.z,a0.w,a1.x,a1.y,a1.z,a1.w};
            float bv[4] = {b4.x,b4.y,b4.z,b4.w};
#pragma unroll
            for (int i = 0; i < 8; i++)
#pragma unroll
                for (int j = 0; j < 4; j++)
                    acc[i][j] = fmaf(a[i], bv[j], acc[i][j]);
        }
        if (pf) {
            int nb = buf ^ 1;
            if (tid < 128) {
#pragma unroll
                for (int e = 0; e < 16; e++) As[nb][e][tid] = pa[e];
            }
#pragma unroll
            for (int e = 0; e < 4; e++) Bs[nb][bk + e][bn] = pb[e];
        }
        __syncthreads();
        buf ^= 1;
    }

#pragma unroll
    for (int i = 0; i < 8; i++) {
        int m = m0 + ty*8 + i;
        *(float4*)(g_projm + ((long long)zb * LL + m) * 48 + txx*4) =
            make_float4(acc[i][0], acc[i][1], acc[i][2], acc[i][3]);
    }
}

// ------------------------- depthwise 1x7 + 7x1 fused --------------------------
__global__ void dwconv_k(const float* __restrict__ p,
                         const float* __restrict__ wh, const float* __restrict__ wv,
                         const float* __restrict__ hg, const float* __restrict__ hb,
                         const float* __restrict__ vg, const float* __restrict__ vb,
                         float* __restrict__ out)
{
    int idx = blockIdx.x * blockDim.x + threadIdx.x;
    if (idx >= BB * CC * HWW) return;
    int l = idx % HWW;
    int c = (idx / HWW) % CC;
    int y = l / WW, x = l % WW;
    const float* base = p + (idx - l);
    float sh = 0.f, sv = 0.f;
#pragma unroll
    for (int j = 0; j < 7; j++) {
        int xx = x - 3 + j;
        if (xx >= 0 && xx < WW) sh += base[y * WW + xx] * wh[c * 7 + j];
        int yy = y - 3 + j;
        if (yy >= 0 && yy < HH) sv += base[yy * WW + x] * wv[c * 7 + j];
    }
    float rh = fmaxf(sh * (hg[c] * BNF) + hb[c], 0.f);
    float rv = fmaxf(sv * (vg[c] * BNF) + vb[c], 0.f);
    out[idx] = rh + rv;
}

// ------------------------- layernorm over C -----------------------------------
__global__ void ln_stats_k(const float* __restrict__ x)
{
    int l = blockIdx.x * blockDim.x + threadIdx.x;
    int b = blockIdx.y;
    if (l >= HWW) return;
    const float* xp = x + (long long)b * CC * HWW + l;
    float s = 0.f, ss = 0.f;
#pragma unroll 8
    for (int c = 0; c < CC; c++) { float v = xp[(long long)c * HWW]; s += v; ss += v * v; }
    float mu = s * (1.f / CC);
    float var = ss * (1.f / CC) - mu * mu;
    g_mu[b * HWW + l] = mu;
    g_rstd[b * HWW + l] = rsqrtf(var + 1e-5f);
}

__global__ void trans_norm_k(const float* __restrict__ x,
                             const float* __restrict__ lng, const float* __restrict__ lnb)
{
    __shared__ float tile[32][33];
    int b = blockIdx.z;
    int l0 = blockIdx.x * 32, c0 = blockIdx.y * 32;
    int tx = threadIdx.x, ty = threadIdx.y;   // (32,8)
#pragma unroll
    for (int i = 0; i < 4; i++) {
        int c = c0 + ty + i * 8;
        tile[ty + i * 8][tx] = x[((long long)b * CC + c) * HWW + l0 + tx];
    }
    __syncthreads();
#pragma unroll
    for (int i = 0; i < 4; i++) {
        int l = l0 + ty + i * 8;
        int c = c0 + tx;
        float v = (tile[tx][ty + i * 8] - g_mu[b * HWW + l]) * g_rstd[b * HWW + l];
        g_xn[((long long)b * HWW + l) * CC + c] = v * lng[c] + lnb[c];
    }
}

// -------- causal depthwise conv1d + silu, chunked, smem map -------------------
#define CCT 64
__global__ void __launch_bounds__(512) conv1d_k(const float* __restrict__ cw,
                                                const float* __restrict__ cb)
{
    __shared__ int sl[CCT + 3];
    int d = threadIdx.x;     // 512
    int t0 = blockIdx.x * CCT;
    int b = blockIdx.y;
    int dir = blockIdx.z;
    if (d < CCT + 3) {
        int tt = t0 - 3 + d;
        sl[d] = (tt >= 0) ? g_map[dir * LL + tt] : 0;
    }
    __syncthreads();
    float w0 = cw[d * 4 + 0], w1 = cw[d * 4 + 1], w2 = cw[d * 4 + 2], w3 = cw[d * 4 + 3];
    float bias = cb[d];
    const float* xzb = g_xz + (long long)b * LL * 1024 + d;
    float x0 = 0.f, x1 = 0.f, x2 = 0.f;
    if (t0 > 0) {
        x0 = xzb[(long long)sl[0] * 1024];
        x1 = xzb[(long long)sl[1] * 1024];
        x2 = xzb[(long long)sl[2] * 1024];
    }
    float xn = xzb[(long long)sl[3] * 1024];
    float* yo = &g_xm[(((long long)dir * BB + b) * LL + t0) * DI + d];
    for (int i = 0; i < CCT; i++) {
        float xnn = (i + 1 < CCT) ? xzb[(long long)sl[i + 4] * 1024] : 0.f;
        float s = bias + w0 * x0 + w1 * x1 + w2 * x2 + w3 * xn;
        yo[(long long)i * DI] = silu_f(s);
        x0 = x1; x1 = x2; x2 = xn; xn = xnn;
    }
}

// ------- dt = softplus(...), packs (dt, dt*x, x, 0) for the scan --------------
#define DTT 16
__global__ void __launch_bounds__(512) dt_k(const float* __restrict__ dtbias)
{
    __shared__ float pr[DTT][16];
    int d = threadIdx.x;
    int t0 = blockIdx.x * DTT;
    int b = blockIdx.y, dir = blockIdx.z;
    long long row0 = ((long long)dir * BB + b) * LL + t0;
    if (d < DTT * 16) {
        int ti = d >> 4, r = d & 15;
        pr[ti][r] = g_projm[(row0 + ti) * 48 + r];
    }
    float wreg[16];
#pragma unroll
    for (int r = 0; r < 16; r++) wreg[r] = g_dtwT[r * DI + d];
    float bias = dtbias[d];
    __syncthreads();
    const float* xmp = &g_xm[row0 * DI + d];
    float4* out = &g_dtq[row0 * DI + d];
#pragma unroll 4
    for (int t = 0; t < DTT; t++) {
        float acc = bias;
#pragma unroll
        for (int r = 0; r < 16; r++) acc = fmaf(pr[t][r], wreg[r], acc);
        float dt = (acc > 15.f) ? acc : log1pf(expf(acc));
        float xv = xmp[(long long)t * DI];
        out[(long long)t * DI] = make_float4(dt, dt * xv, xv, 0.f);
    }
}

// ------------------------- selective scan (PF=8, packed loads) ----------------
__global__ void __launch_bounds__(128) scan_k(const float* __restrict__ A_log,
                                              const float* __restrict__ Dp)
{
    int tid = threadIdx.x;
    int lane = tid & 31;
    int gwarp = blockIdx.x * 4 + (tid >> 5);          // 0..2047
    int dir = gwarp >> 9;
    int b = (gwarp >> 8) & 1;
    int d = ((gwarp & 255) << 1) | (lane >> 4);
    int s = lane & 15;

    float Av = -expf(A_log[d * 16 + s]);
    float Dv = Dp[d];
    long long dbase = ((long long)dir * BB + b) * LL;
    const float4* pq  = g_dtq + dbase * DI + d;
    const float2* pbc = reinterpret_cast<const float2*>(g_projm) + dbase * 24 + 8 + s;
    __nv_bfloat16* py = g_y + dbase * DI + d;

    const int PF = 8;
    float4 f_q[PF];
    float2 f_bc[PF];
#pragma unroll
    for (int i = 0; i < PF; i++) {
        f_q[i]  = pq[i * DI];
        f_bc[i] = pbc[i * 24];
    }
    const float4* qq  = pq + PF * DI;
    const float2* qbc = pbc + PF * 24;

    float h = 0.f;
    for (int t0 = 0; t0 < LL; t0 += PF) {
        bool pf = (t0 + PF < LL);
#pragma unroll
        for (int i = 0; i < PF; i++) {
            float dtv = f_q[i].x, dtx = f_q[i].y, xv = f_q[i].z;
            float Bv = f_bc[i].x, Cv = f_bc[i].y;
            if (pf) {
                f_q[i]  = qq[i * DI];
                f_bc[i] = qbc[i * 24];
            }
            float dA = __expf(dtv * Av);
            h = fmaf(dA, h, dtx * Bv);
            float part = h * Cv;
            part += __shfl_xor_sync(0xffffffffu, part, 1);
            part += __shfl_xor_sync(0xffffffffu, part, 2);
            part += __shfl_xor_sync(0xffffffffu, part, 4);
            part += __shfl_xor_sync(0xffffffffu, part, 8);
            if (s == 0) py[i * DI] = __float2bfloat16(fmaf(Dv, xv, part));
        }
        qq += PF * DI; qbc += PF * 24; py += PF * DI;
    }
}

// ----- gather 4 directions back to natural order, apply silu(z) gate ----------
__global__ void ysum_k()
{
    long long i = (long long)blockIdx.x * blockDim.x + threadIdx.x;
    if (i >= (long long)BL * DI) return;
    int d = (int)(i & (DI - 1));
    int l = (int)((i / DI) % LL);
    int b = (int)(i / ((long long)LL * DI));
    int t2 = (l % WW) * HH + l / WW;   // transpose involution (H==W==48)
    const long long st = (long long)BB * LL * DI;
    long long bb = (long long)b * LL * DI;
    float y = __bfloat162float(g_y[bb + (long long)l * DI + d])
            + __bfloat162float(g_y[st + bb + (long long)(LL - 1 - l) * DI + d])
            + __bfloat162float(g_y[2 * st + bb + (long long)t2 * DI + d])
            + __bfloat162float(g_y[3 * st + bb + (long long)(LL - 1 - t2) * DI + d]);
    float z = g_xz[((long long)b * LL + l) * 1024 + DI + d];
    g_ysum[((long long)b * LL + l) * DI + d] = y * silu_f(z);
}

// ------------------------- SE head --------------------------------------------
__global__ void mean_k()
{
    int c = blockIdx.x, b = blockIdx.y;
    long long base = ((long long)b * CC + c) * HWW;
    float s = 0.f;
    for (int l = threadIdx.x; l < HWW; l += 256)
        s += g_featloc[base + l] + g_featglob[base + l];
    __shared__ float red[256];
    red[threadIdx.x] = s;
    __syncthreads();
    for (int o = 128; o; o >>= 1) {
        if (threadIdx.x < o) red[threadIdx.x] += red[threadIdx.x + o];
        __syncthreads();
    }
    if (threadIdx.x == 0) g_sv[b * CC + c] = red[0] / (float)HWW;
}

__global__ void fc_k(const float* __restrict__ fc1, const float* __restrict__ fc2)
{
    int b = blockIdx.x;
    __shared__ float ss[CC], tt[16];
    int tid = threadIdx.x;   // 256
    ss[tid] = g_sv[b * CC + tid];
    __syncthreads();
    if (tid < 16) {
        float a = 0.f;
        for (int c = 0; c < CC; c++) a += ss[c] * fc1[tid * CC + c];
        tt[tid] = fmaxf(a, 0.f);
    }
    __syncthreads();
    float z0 = 0.f, z1 = 0.f;
#pragma unroll
    for (int m = 0; m < 16; m++) {
        z0 += tt[m] * fc2[tid * 16 + m];
        z1 += tt[m] * fc2[(CC + tid) * 16 + m];
    }
    float mx = fmaxf(z0, z1);
    float e0 = expf(z0 - mx), e1 = expf(z1 - mx);
    float w0 = e0 / (e0 + e1);
    g_wv[b * 2 * CC + tid] = w0;
    g_wv[b * 2 * CC + CC + tid] = 1.f - w0;
}

__global__ void final_k(float* __restrict__ out)
{
    long long i = (long long)blockIdx.x * 256 + threadIdx.x;
    if (i >= (long long)BB * CC * HWW) return;
    int c = (int)((i / HWW) % CC);
    int b = (int)(i / ((long long)CC * HWW));
    out[i] = g_wv[b * 2 * CC + c] * g_featloc[i] + g_wv[b * 2 * CC + CC + c] * g_featglob[i];
}

// ------------------------- launch ---------------------------------------------
extern "C" void kernel_launch(void* const* d_in, const int* in_sizes, int n_in,
                              void* d_out, int out_size)
{
    const float* x        = (const float*)d_in[0];
    const float* reduce_w = (const float*)d_in[1];
    const float* bn0_g    = (const float*)d_in[2];
    const float* bn0_b    = (const float*)d_in[3];
    const float* proj_w   = (const float*)d_in[4];
    const float* bn1_g    = (const float*)d_in[5];
    const float* bn1_b    = (const float*)d_in[6];
    const float* dwh_w    = (const float*)d_in[7];
    const float* bnh_g    = (const float*)d_in[8];
    const float* bnh_b    = (const float*)d_in[9];
    const float* dwv_w    = (const float*)d_in[10];
    const float* bnv_g    = (const float*)d_in[11];
    const float* bnv_b    = (const float*)d_in[12];
    const float* fus_w    = (const float*)d_in[13];
    const float* fus_b    = (const float*)d_in[14];
    const float* ln_g     = (const float*)d_in[15];
    const float* ln_b     = (const float*)d_in[16];
    const float* in_w     = (const float*)d_in[17];
    const float* conv_w   = (const float*)d_in[18];
    const float* conv_b   = (const float*)d_in[19];
    const float* xproj_w  = (const float*)d_in[20];
    const float* dt_w     = (const float*)d_in[21];
    const float* dt_b     = (const float*)d_in[22];
    const float* A_log    = (const float*)d_in[23];
    const float* Dp       = (const float*)d_in[24];
    const float* out_w    = (const float*)d_in[25];
    const float* fc1_w    = (const float*)d_in[26];
    const float* fc2_w    = (const float*)d_in[27];

    float *xred, *p, *hv, *featloc, *featglob, *xn, *xz;
    cudaGetSymbolAddress((void**)&xred, g_xred);
    cudaGetSymbolAddress((void**)&p, g_p);
    cudaGetSymbolAddress((void**)&hv, g_hv);
    cudaGetSymbolAddress((void**)&featloc, g_featloc);
    cudaGetSymbolAddress((void**)&featglob, g_featglob);
    cudaGetSymbolAddress((void**)&xn, g_xn);
    cudaGetSymbolAddress((void**)&xz, g_xz);
    float* ysum;
    cudaGetSymbolAddress((void**)&ysum, g_ysum);

    // 0) one-time weight prep (maps, transposes, permutations)
    init_misc_k<<<96, 256>>>(dt_w, xproj_w);
    // 1) x = relu(bn0(reduce_w @ xin))
    gemm128<1, false><<<dim3(36, 2, BB), 256>>>(reduce_w, x, xred, 256, 2304, 512,
        0, (long long)CIN * HWW, (long long)CC * HWW, bn0_g, bn0_b, (const float*)0, 0);
    // 2,3) layernorm over C (shared by all directions)
    ln_stats_k<<<dim3((HWW + 255) / 256, BB), 256>>>(xred);
    trans_norm_k<<<dim3(HWW / 32, CC / 32, BB), dim3(32, 8)>>>(xred, ln_g, ln_b);
    // 4) in_proj: xz = xn @ in_w.T
    gemm_nt_big<<<dim3(8, 18, BB), 256>>>(xn, in_w, xz, 2304, 1024, 256,
        (long long)LL * CC, (long long)LL * 1024);
    // 5) causal conv1d + silu -> scan-ordered xm
    conv1d_k<<<dim3(LL / CCT, BB, 4), 512>>>(conv_w, conv_b);
    // 6) xproj per (dir,b) with permuted weights (B/C interleaved output)
    gemm_xproj<<<dim3(18, 8), 192>>>();
    // 7) dt pack (dt, dt*x, x)
    dt_k<<<dim3(LL / DTT, BB, 4), 512>>>(dt_b);
    // 8) selective scan
    scan_k<<<512, 128>>>(A_log, Dp);
    // 9) gather directions + silu(z) gate
    ysum_k<<<(BL * DI + 255) / 256, 256>>>();
    // 10) feat_global = 0.25 * (out_w @ ysum) + x
    gemm128<3, true><<<dim3(36, 2, BB), 256>>>(out_w, ysum, featglob, 256, 2304, 512,
        0, (long long)LL * DI, (long long)CC * HWW, (const float*)0, (const float*)0,
        xred, (long long)CC * HWW);
    // 11) p = relu(bn1(proj_w @ x))
    gemm128<1, false><<<dim3(36, 2, BB), 256>>>(proj_w, xred, p, 256, 2304, 256,
        0, (long long)CC * HWW, (long long)CC * HWW, bn1_g, bn1_b, (const float*)0, 0);
    // 12) depthwise h+v fused
    dwconv_k<<<(BB * CC * HWW + 255) / 256, 256>>>(p, dwh_w, dwv_w,
                                                   bnh_g, bnh_b, bnv_g, bnv_b, hv);
    // 13) feat_local = fus_w @ (h+v) + fus_b
    gemm128<2, false><<<dim3(36, 2, BB), 256>>>(fus_w, hv, featloc, 256, 2304, 256,
        0, (long long)CC * HWW, (long long)CC * HWW, (const float*)0, fus_b, (const float*)0, 0);
    // 14-16) SE head + final combine
    mean_k<<<dim3(CC, BB), 256>>>();
    fc_k<<<BB, 256>>>(fc1_w, fc2_w);
    final_k<<<(BB * CC * HWW + 255) / 256, 256>>>((float*)d_out);
}

// round 7
// speedup vs baseline: 1.1103x; 1.1103x over previous
#include <cuda_runtime.h>
#include <cuda_bf16.h>
#include <math.h>

#define BB  2
#define CIN 512
#define CC  256
#define HH  48
#define WW  48
#define HWW 2304
#define LL  2304
#define DI  512
#define BL  (BB*LL)
#define BNF 0.9999950000374997f   /* 1/sqrt(1+1e-5) */

// ------------------------- static scratch (no allocs) -------------------------
__device__ __align__(256) float g_xred[BB*CC*HWW];
__device__ __align__(256) float g_p[BB*CC*HWW];
__device__ __align__(256) float g_hv[BB*CC*HWW];
__device__ __align__(256) float g_featloc[BB*CC*HWW];
__device__ __align__(256) float g_featglob[BB*CC*HWW];
__device__ __align__(256) float g_mu[BB*HWW];
__device__ __align__(256) float g_rstd[BB*HWW];
__device__ __align__(256) float g_xn[BL*CC];          // (b,l,c)
__device__ __align__(256) float g_xz[BL*2*DI];        // (b,l,1024): xm0 | z
__device__ __align__(256) float g_xm[4*BL*DI];        // (dir,b,t,d) SCAN order
__device__ __align__(256) float g_projm[4*BL*48];     // (dir,b,t,48): [dt16][B,C interleaved]
__device__ __align__(256) float g_dtb[4*BL*DI];       // SCAN order
__device__ __align__(256) __nv_bfloat16 g_y[4*BL*DI]; // SCAN order, ungated, bf16
__device__ __align__(256) float g_ysum[BL*DI];        // natural order, gated
__device__ __align__(256) float g_dtwT[16*DI];        // transposed dt_w
__device__ __align__(256) float g_xpw[48*DI];         // row-permuted xproj_w
__device__ __align__(256) int   g_map[4*LL];          // dir,t -> l
__device__ __align__(256) float g_sv[BB*CC];
__device__ __align__(256) float g_wv[BB*2*CC];

__device__ __forceinline__ int seq_map(int dir, int t) {
    if (dir == 0) return t;
    if (dir == 1) return LL - 1 - t;
    int u = (dir == 2) ? t : (LL - 1 - t);
    int h = u % HH, w = u / HH;
    return h * WW + w;
}

__device__ __forceinline__ float silu_f(float x) { return x / (1.f + __expf(-x)); }

// ------------------ one-time weight/layout prep --------------------------------
__global__ void init_misc_k(const float* __restrict__ dtw, const float* __restrict__ xpw)
{
    int i = blockIdx.x * 256 + threadIdx.x;
    if (i < 16 * DI) {                       // dt_w transpose
        int dd = i >> 4, r = i & 15;
        g_dtwT[r * DI + dd] = dtw[i];
    }
    if (i < 4 * LL) {                        // scan-order maps
        int dir = i / LL, t = i % LL;
        g_map[i] = seq_map(dir, t);
    }
    if (i < 48 * DI) {                       // xproj weight row-permutation
        int j = i >> 9, k = i & 511;
        int src = (j < 16) ? j
                : (((j - 16) & 1) ? 32 + ((j - 16) >> 1) : 16 + ((j - 16) >> 1));
        g_xpw[i] = xpw[src * DI + k];
    }
}

// ---------------- 128x128 SGEMM, 8x8 microtile, NT (round-5 version) ----------
__global__ void __launch_bounds__(256) gemm_nt_big(
    const float* __restrict__ A, const float* __restrict__ B, float* __restrict__ C,
    int M, int N, int K, long long sA, long long sC)
{
    __shared__ float As[16][132];
    __shared__ float Bs[16][132];
    int tid = threadIdx.x;
    int m0 = blockIdx.y * 128, n0 = blockIdx.x * 128;
    int r = tid >> 1;              // 0..127
    int kk = (tid & 1) * 8;        // 0 or 8
    const float* aptr = A + (long long)blockIdx.z * sA + (long long)(m0 + r) * K + kk;
    const float* bptr = B + (long long)(n0 + r) * K + kk;
    int tx = tid & 15, ty = tid >> 4;

    float4 pa0 = *(const float4*)(aptr);
    float4 pa1 = *(const float4*)(aptr + 4);
    float4 pb0 = *(const float4*)(bptr);
    float4 pb1 = *(const float4*)(bptr + 4);

    float acc[8][8] = {};

    for (int k0 = 0; k0 < K; k0 += 16) {
        As[kk+0][r]=pa0.x; As[kk+1][r]=pa0.y; As[kk+2][r]=pa0.z; As[kk+3][r]=pa0.w;
        As[kk+4][r]=pa1.x; As[kk+5][r]=pa1.y; As[kk+6][r]=pa1.z; As[kk+7][r]=pa1.w;
        Bs[kk+0][r]=pb0.x; Bs[kk+1][r]=pb0.y; Bs[kk+2][r]=pb0.z; Bs[kk+3][r]=pb0.w;
        Bs[kk+4][r]=pb1.x; Bs[kk+5][r]=pb1.y; Bs[kk+6][r]=pb1.z; Bs[kk+7][r]=pb1.w;
        __syncthreads();
        if (k0 + 16 < K) {
            aptr += 16; bptr += 16;
            pa0 = *(const float4*)(aptr);
            pa1 = *(const float4*)(aptr + 4);
            pb0 = *(const float4*)(bptr);
            pb1 = *(const float4*)(bptr + 4);
        }
#pragma unroll
        for (int k = 0; k < 16; k++) {
            float4 a0 = *(const float4*)&As[k][ty*8];
            float4 a1 = *(const float4*)&As[k][ty*8+4];
            float4 b0 = *(const float4*)&Bs[k][tx*8];
            float4 b1 = *(const float4*)&Bs[k][tx*8+4];
            float a[8] = {a0.x,a0.y,a0.z,a0.w,a1.x,a1.y,a1.z,a1.w};
            float b[8] = {b0.x,b0.y,b0.z,b0.w,b1.x,b1.y,b1.z,b1.w};
#pragma unroll
            for (int i = 0; i < 8; i++)
#pragma unroll
                for (int j = 0; j < 8; j++)
                    acc[i][j] = fmaf(a[i], b[j], acc[i][j]);
        }
        __syncthreads();
    }

    float* Cb = C + (long long)blockIdx.z * sC;
#pragma unroll
    for (int i = 0; i < 8; i++) {
        int m = m0 + ty*8 + i;
        *(float4*)(Cb + (long long)m * N + n0 + tx*8)     = make_float4(acc[i][0],acc[i][1],acc[i][2],acc[i][3]);
        *(float4*)(Cb + (long long)m * N + n0 + tx*8 + 4) = make_float4(acc[i][4],acc[i][5],acc[i][6],acc[i][7]);
    }
}

// ------------------------- 128x64 SGEMM, k-tile 32 (round-5 version) ----------
template<int MODE, bool TB>
__global__ void __launch_bounds__(256) gemm128(
    const float* __restrict__ A, const float* __restrict__ B, float* __restrict__ C,
    int M, int N, int K,
    long long sA, long long sB, long long sC,
    const float* __restrict__ scale, const float* __restrict__ bias,
    const float* __restrict__ extra, long long sE)
{
    __shared__ float As[32][132];
    __shared__ float Bs[32][68];
    const float* Ab = A + (long long)blockIdx.z * sA;
    const float* Bb = B + (long long)blockIdx.z * sB;
    float* Cb = C + (long long)blockIdx.z * sC;
    int tid = threadIdx.x;
    int m0 = blockIdx.y * 128, n0 = blockIdx.x * 64;
    int tx = tid & 15, ty = tid >> 4;

    int arow = tid >> 3;
    int akk = (tid & 7) * 4;
    const float* aptr = Ab + (long long)(m0 + arow) * K + akk;
    const long long astep = (long long)32 * K;

    int bk, bn;
    const float* bptr;
    if (TB) {
        bn = tid >> 3;
        bk = (tid & 7) * 4;
        bptr = Bb + (long long)(n0 + bn) * K + bk;
    } else {
        bk = (tid >> 4) * 2;
        bn = (tid & 15) * 4;
        bptr = Bb + (long long)bk * N + n0 + bn;
    }

    float4 pa[4], pb[2];
#pragma unroll
    for (int i = 0; i < 4; i++) pa[i] = *(const float4*)(aptr + i * astep);
    if (TB) {
        pb[0] = *(const float4*)(bptr);
        pb[1] = *(const float4*)(bptr + astep);
    } else {
        pb[0] = *(const float4*)(bptr);
        pb[1] = *(const float4*)(bptr + N);
    }

    float acc[8][4] = {};

    for (int k0 = 0; k0 < K; k0 += 32) {
#pragma unroll
        for (int i = 0; i < 4; i++) {
            As[akk+0][arow+32*i] = pa[i].x;
            As[akk+1][arow+32*i] = pa[i].y;
            As[akk+2][arow+32*i] = pa[i].z;
            As[akk+3][arow+32*i] = pa[i].w;
        }
        if (TB) {
            Bs[bk+0][bn] = pb[0].x; Bs[bk+1][bn] = pb[0].y;
            Bs[bk+2][bn] = pb[0].z; Bs[bk+3][bn] = pb[0].w;
            Bs[bk+0][bn+32] = pb[1].x; Bs[bk+1][bn+32] = pb[1].y;
            Bs[bk+2][bn+32] = pb[1].z; Bs[bk+3][bn+32] = pb[1].w;
        } else {
            *(float4*)&Bs[bk][bn] = pb[0];
            *(float4*)&Bs[bk+1][bn] = pb[1];
        }
        __syncthreads();
        if (k0 + 32 < K) {
            aptr += 32;
#pragma unroll
            for (int i = 0; i < 4; i++) pa[i] = *(const float4*)(aptr + i * astep);
            if (TB) {
                bptr += 32;
                pb[0] = *(const float4*)(bptr);
                pb[1] = *(const float4*)(bptr + astep);
            } else {
                bptr += (long long)32 * N;
                pb[0] = *(const float4*)(bptr);
                pb[1] = *(const float4*)(bptr + N);
            }
        }
#pragma unroll 8
        for (int k = 0; k < 32; k++) {
            float4 a0 = *(const float4*)&As[k][ty*8];
            float4 a1 = *(const float4*)&As[k][ty*8+4];
            float4 b4 = *(const float4*)&Bs[k][tx*4];
            float a[8] = {a0.x,a0.y,a0.z,a0.w,a1.x,a1.y,a1.z,a1.w};
            float bbv[4] = {b4.x,b4.y,b4.z,b4.w};
#pragma unroll
            for (int i = 0; i < 8; i++)
#pragma unroll
                for (int j = 0; j < 4; j++)
                    acc[i][j] = fmaf(a[i], bbv[j], acc[i][j]);
        }
        __syncthreads();
    }

#pragma unroll
    for (int i = 0; i < 8; i++) {
        int m = m0 + ty*8 + i;
        float sc = 1.f, bi = 0.f;
        if (MODE == 1) { sc = scale[m] * BNF; bi = bias[m]; }
        if (MODE == 2) { bi = bias[m]; }
        int n = n0 + tx*4;
        float v[4];
#pragma unroll
        for (int j = 0; j < 4; j++) {
            float t = acc[i][j];
            if (MODE == 1) t = fmaxf(fmaf(t, sc, bi), 0.f);
            else if (MODE == 2) t = t + bi;
            else if (MODE == 3)
                t = t * 0.25f + extra[(long long)blockIdx.z * sE + (long long)m * N + n + j];
            v[j] = t;
        }
        *(float4*)(Cb + (long long)m * N + n) = make_float4(v[0], v[1], v[2], v[3]);
    }
}

// ---------------- xproj: (dir,b) x [2304 x 48] = xm @ Wperm.T -----------------
// 128x48 tile, 192 threads, 8x4 micro. Writes B/C interleaved layout.
__global__ void __launch_bounds__(192) gemm_xproj()
{
    __shared__ float As[16][132];
    __shared__ float Bs[16][52];
    int tid = threadIdx.x;
    int zb = blockIdx.y;                 // dir*BB+b
    int m0 = blockIdx.x * 128;
    const float* Ab = g_xm + (long long)zb * LL * DI;
    const float* aptr = Ab + (long long)(m0 + tid) * DI;   // valid if tid<128
    int bn = tid >> 2, bk = (tid & 3) * 4;
    const float* bptr = g_xpw + bn * DI + bk;
    int ty = tid / 12, txx = tid % 12;

    float4 pa[4], pbv;
    if (tid < 128) {
#pragma unroll
        for (int j = 0; j < 4; j++) pa[j] = ((const float4*)aptr)[j];
    }
    pbv = *(const float4*)bptr;

    float acc[8][4] = {};
    for (int k0 = 0; k0 < DI; k0 += 16) {
        if (tid < 128) {
#pragma unroll
            for (int j = 0; j < 4; j++) {
                As[j*4+0][tid] = pa[j].x;
                As[j*4+1][tid] = pa[j].y;
                As[j*4+2][tid] = pa[j].z;
                As[j*4+3][tid] = pa[j].w;
            }
        }
        Bs[bk+0][bn] = pbv.x; Bs[bk+1][bn] = pbv.y;
        Bs[bk+2][bn] = pbv.z; Bs[bk+3][bn] = pbv.w;
        __syncthreads();
        if (k0 + 16 < DI) {
            if (tid < 128) {
                const float* an = aptr + k0 + 16;
#pragma unroll
                for (int j = 0; j < 4; j++) pa[j] = ((const float4*)an)[j];
            }
            pbv = *(const float4*)(bptr + k0 + 16);
        }
#pragma unroll
        for (int k = 0; k < 16; k++) {
            float4 a0 = *(const float4*)&As[k][ty*8];
            float4 a1 = *(const float4*)&As[k][ty*8+4];
            float4 b4 = *(const float4*)&Bs[k][txx*4];
            float a[8] = {a0.x,a0.y,a0.z,a0.w,a1.x,a1.y,a1.z,a1.w};
            float bv[4] = {b4.x,b4.y,b4.z,b4.w};
#pragma unroll
            for (int i = 0; i < 8; i++)
#pragma unroll
                for (int j = 0; j < 4; j++)
                    acc[i][j] = fmaf(a[i], bv[j], acc[i][j]);
        }
        __syncthreads();
    }

#pragma unroll
    for (int i = 0; i < 8; i++) {
        int m = m0 + ty*8 + i;
        *(float4*)(g_projm + ((long long)zb * LL + m) * 48 + txx*4) =
            make_float4(acc[i][0], acc[i][1], acc[i][2], acc[i][3]);
    }
}

// ------------------------- depthwise 1x7 + 7x1 fused --------------------------
__global__ void dwconv_k(const float* __restrict__ p,
                         const float* __restrict__ wh, const float* __restrict__ wv,
                         const float* __restrict__ hg, const float* __restrict__ hb,
                         const float* __restrict__ vg, const float* __restrict__ vb,
                         float* __restrict__ out)
{
    int idx = blockIdx.x * blockDim.x + threadIdx.x;
    if (idx >= BB * CC * HWW) return;
    int l = idx % HWW;
    int c = (idx / HWW) % CC;
    int y = l / WW, x = l % WW;
    const float* base = p + (idx - l);
    float sh = 0.f, sv = 0.f;
#pragma unroll
    for (int j = 0; j < 7; j++) {
        int xx = x - 3 + j;
        if (xx >= 0 && xx < WW) sh += base[y * WW + xx] * wh[c * 7 + j];
        int yy = y - 3 + j;
        if (yy >= 0 && yy < HH) sv += base[yy * WW + x] * wv[c * 7 + j];
    }
    float rh = fmaxf(sh * (hg[c] * BNF) + hb[c], 0.f);
    float rv = fmaxf(sv * (vg[c] * BNF) + vb[c], 0.f);
    out[idx] = rh + rv;
}

// ------------------------- layernorm over C -----------------------------------
__global__ void ln_stats_k(const float* __restrict__ x)
{
    int l = blockIdx.x * blockDim.x + threadIdx.x;
    int b = blockIdx.y;
    if (l >= HWW) return;
    const float* xp = x + (long long)b * CC * HWW + l;
    float s = 0.f, ss = 0.f;
#pragma unroll 8
    for (int c = 0; c < CC; c++) { float v = xp[(long long)c * HWW]; s += v; ss += v * v; }
    float mu = s * (1.f / CC);
    float var = ss * (1.f / CC) - mu * mu;
    g_mu[b * HWW + l] = mu;
    g_rstd[b * HWW + l] = rsqrtf(var + 1e-5f);
}

__global__ void trans_norm_k(const float* __restrict__ x,
                             const float* __restrict__ lng, const float* __restrict__ lnb)
{
    __shared__ float tile[32][33];
    int b = blockIdx.z;
    int l0 = blockIdx.x * 32, c0 = blockIdx.y * 32;
    int tx = threadIdx.x, ty = threadIdx.y;   // (32,8)
#pragma unroll
    for (int i = 0; i < 4; i++) {
        int c = c0 + ty + i * 8;
        tile[ty + i * 8][tx] = x[((long long)b * CC + c) * HWW + l0 + tx];
    }
    __syncthreads();
#pragma unroll
    for (int i = 0; i < 4; i++) {
        int l = l0 + ty + i * 8;
        int c = c0 + tx;
        float v = (tile[tx][ty + i * 8] - g_mu[b * HWW + l]) * g_rstd[b * HWW + l];
        g_xn[((long long)b * HWW + l) * CC + c] = v * lng[c] + lnb[c];
    }
}

// -------- causal depthwise conv1d + silu, chunked, smem map -------------------
#define CCT 64
__global__ void __launch_bounds__(512) conv1d_k(const float* __restrict__ cw,
                                                const float* __restrict__ cb)
{
    __shared__ int sl[CCT + 3];
    int d = threadIdx.x;     // 512
    int t0 = blockIdx.x * CCT;
    int b = blockIdx.y;
    int dir = blockIdx.z;
    if (d < CCT + 3) {
        int tt = t0 - 3 + d;
        sl[d] = (tt >= 0) ? g_map[dir * LL + tt] : 0;
    }
    __syncthreads();
    float w0 = cw[d * 4 + 0], w1 = cw[d * 4 + 1], w2 = cw[d * 4 + 2], w3 = cw[d * 4 + 3];
    float bias = cb[d];
    const float* xzb = g_xz + (long long)b * LL * 1024 + d;
    float x0 = 0.f, x1 = 0.f, x2 = 0.f;
    if (t0 > 0) {
        x0 = xzb[(long long)sl[0] * 1024];
        x1 = xzb[(long long)sl[1] * 1024];
        x2 = xzb[(long long)sl[2] * 1024];
    }
    float xn = xzb[(long long)sl[3] * 1024];
    float* yo = &g_xm[(((long long)dir * BB + b) * LL + t0) * DI + d];
    for (int i = 0; i < CCT; i++) {
        float xnn = (i + 1 < CCT) ? xzb[(long long)sl[i + 4] * 1024] : 0.f;
        float s = bias + w0 * x0 + w1 * x1 + w2 * x2 + w3 * xn;
        yo[(long long)i * DI] = silu_f(s);
        x0 = x1; x1 = x2; x2 = xn; xn = xnn;
    }
}

// ---------- dt = softplus(proj[:,:16] @ dt_w.T + dt_b), 16 t per block --------
#define DTT 16
__global__ void __launch_bounds__(512) dt_k(const float* __restrict__ dtbias)
{
    __shared__ float pr[DTT][16];
    int d = threadIdx.x;
    int t0 = blockIdx.x * DTT;
    int b = blockIdx.y, dir = blockIdx.z;
    long long row0 = ((long long)dir * BB + b) * LL + t0;
    if (d < DTT * 16) {
        int ti = d >> 4, r = d & 15;
        pr[ti][r] = g_projm[(row0 + ti) * 48 + r];
    }
    float wreg[16];
#pragma unroll
    for (int r = 0; r < 16; r++) wreg[r] = g_dtwT[r * DI + d];
    float bias = dtbias[d];
    __syncthreads();
    float* out = &g_dtb[row0 * DI + d];
#pragma unroll 4
    for (int t = 0; t < DTT; t++) {
        float acc = bias;
#pragma unroll
        for (int r = 0; r < 16; r++) acc = fmaf(pr[t][r], wreg[r], acc);
        float dt = (acc > 15.f) ? acc : log1pf(expf(acc));
        out[(long long)t * DI] = dt;
    }
}

// ------------------------- selective scan (PF=8, float2 BC) -------------------
__global__ void __launch_bounds__(128) scan_k(const float* __restrict__ A_log,
                                              const float* __restrict__ Dp)
{
    int tid = threadIdx.x;
    int lane = tid & 31;
    int gwarp = blockIdx.x * 4 + (tid >> 5);          // 0..2047
    int dir = gwarp >> 9;
    int b = (gwarp >> 8) & 1;
    int d = ((gwarp & 255) << 1) | (lane >> 4);
    int s = lane & 15;

    float Av = -expf(A_log[d * 16 + s]);
    float Dv = Dp[d];
    long long dbase = ((long long)dir * BB + b) * LL;
    const float* pdt = g_dtb + dbase * DI + d;
    const float* pxm = g_xm + dbase * DI + d;
    const float2* pbc = reinterpret_cast<const float2*>(g_projm) + dbase * 24 + 8 + s;
    __nv_bfloat16* py = g_y + dbase * DI + d;

    const int PF = 8;
    float f_dt[PF], f_x[PF];
    float2 f_bc[PF];
#pragma unroll
    for (int i = 0; i < PF; i++) {
        f_dt[i] = pdt[i * DI];
        f_x[i]  = pxm[i * DI];
        f_bc[i] = pbc[i * 24];
    }
    const float* qdt = pdt + PF * DI;
    const float* qxm = pxm + PF * DI;
    const float2* qbc = pbc + PF * 24;

    float h = 0.f;
    for (int t0 = 0; t0 < LL; t0 += PF) {
        bool pf = (t0 + PF < LL);
#pragma unroll
        for (int i = 0; i < PF; i++) {
            float dtv = f_dt[i], xv = f_x[i];
            float Bv = f_bc[i].x, Cv = f_bc[i].y;
            if (pf) {
                f_dt[i] = qdt[i * DI];
                f_x[i]  = qxm[i * DI];
                f_bc[i] = qbc[i * 24];
            }
            float dA = __expf(dtv * Av);
            h = fmaf(dA, h, dtv * xv * Bv);
            float part = h * Cv;
            part += __shfl_xor_sync(0xffffffffu, part, 1);
            part += __shfl_xor_sync(0xffffffffu, part, 2);
            part += __shfl_xor_sync(0xffffffffu, part, 4);
            part += __shfl_xor_sync(0xffffffffu, part, 8);
            if (s == 0) py[i * DI] = __float2bfloat16(fmaf(Dv, xv, part));
        }
        qdt += PF * DI; qxm += PF * DI; qbc += PF * 24; py += PF * DI;
    }
}

// ----- gather 4 directions back to natural order, apply silu(z) gate ----------
__global__ void ysum_k()
{
    long long i = (long long)blockIdx.x * blockDim.x + threadIdx.x;
    if (i >= (long long)BL * DI) return;
    int d = (int)(i & (DI - 1));
    int l = (int)((i / DI) % LL);
    int b = (int)(i / ((long long)LL * DI));
    int t2 = (l % WW) * HH + l / WW;   // transpose involution (H==W==48)
    const long long st = (long long)BB * LL * DI;
    long long bb = (long long)b * LL * DI;
    float y = __bfloat162float(g_y[bb + (long long)l * DI + d])
            + __bfloat162float(g_y[st + bb + (long long)(LL - 1 - l) * DI + d])
            + __bfloat162float(g_y[2 * st + bb + (long long)t2 * DI + d])
            + __bfloat162float(g_y[3 * st + bb + (long long)(LL - 1 - t2) * DI + d]);
    float z = g_xz[((long long)b * LL + l) * 1024 + DI + d];
    g_ysum[((long long)b * LL + l) * DI + d] = y * silu_f(z);
}

// ------------------------- SE head --------------------------------------------
__global__ void mean_k()
{
    int c = blockIdx.x, b = blockIdx.y;
    long long base = ((long long)b * CC + c) * HWW;
    float s = 0.f;
    for (int l = threadIdx.x; l < HWW; l += 256)
        s += g_featloc[base + l] + g_featglob[base + l];
    __shared__ float red[256];
    red[threadIdx.x] = s;
    __syncthreads();
    for (int o = 128; o; o >>= 1) {
        if (threadIdx.x < o) red[threadIdx.x] += red[threadIdx.x + o];
        __syncthreads();
    }
    if (threadIdx.x == 0) g_sv[b * CC + c] = red[0] / (float)HWW;
}

__global__ void fc_k(const float* __restrict__ fc1, const float* __restrict__ fc2)
{
    int b = blockIdx.x;
    __shared__ float ss[CC], tt[16];
    int tid = threadIdx.x;   // 256
    ss[tid] = g_sv[b * CC + tid];
    __syncthreads();
    if (tid < 16) {
        float a = 0.f;
        for (int c = 0; c < CC; c++) a += ss[c] * fc1[tid * CC + c];
        tt[tid] = fmaxf(a, 0.f);
    }
    __syncthreads();
    float z0 = 0.f, z1 = 0.f;
#pragma unroll
    for (int m = 0; m < 16; m++) {
        z0 += tt[m] * fc2[tid * 16 + m];
        z1 += tt[m] * fc2[(CC + tid) * 16 + m];
    }
    float mx = fmaxf(z0, z1);
    float e0 = expf(z0 - mx), e1 = expf(z1 - mx);
    float w0 = e0 / (e0 + e1);
    g_wv[b * 2 * CC + tid] = w0;
    g_wv[b * 2 * CC + CC + tid] = 1.f - w0;
}

__global__ void final_k(float* __restrict__ out)
{
    long long i = (long long)blockIdx.x * 256 + threadIdx.x;
    if (i >= (long long)BB * CC * HWW) return;
    int c = (int)((i / HWW) % CC);
    int b = (int)(i / ((long long)CC * HWW));
    out[i] = g_wv[b * 2 * CC + c] * g_featloc[i] + g_wv[b * 2 * CC + CC + c] * g_featglob[i];
}

// ------------------------- launch ---------------------------------------------
extern "C" void kernel_launch(void* const* d_in, const int* in_sizes, int n_in,
                              void* d_out, int out_size)
{
    const float* x        = (const float*)d_in[0];
    const float* reduce_w = (const float*)d_in[1];
    const float* bn0_g    = (const float*)d_in[2];
    const float* bn0_b    = (const float*)d_in[3];
    const float* proj_w   = (const float*)d_in[4];
    const float* bn1_g    = (const float*)d_in[5];
    const float* bn1_b    = (const float*)d_in[6];
    const float* dwh_w    = (const float*)d_in[7];
    const float* bnh_g    = (const float*)d_in[8];
    const float* bnh_b    = (const float*)d_in[9];
    const float* dwv_w    = (const float*)d_in[10];
    const float* bnv_g    = (const float*)d_in[11];
    const float* bnv_b    = (const float*)d_in[12];
    const float* fus_w    = (const float*)d_in[13];
    const float* fus_b    = (const float*)d_in[14];
    const float* ln_g     = (const float*)d_in[15];
    const float* ln_b     = (const float*)d_in[16];
    const float* in_w     = (const float*)d_in[17];
    const float* conv_w   = (const float*)d_in[18];
    const float* conv_b   = (const float*)d_in[19];
    const float* xproj_w  = (const float*)d_in[20];
    const float* dt_w     = (const float*)d_in[21];
    const float* dt_b     = (const float*)d_in[22];
    const float* A_log    = (const float*)d_in[23];
    const float* Dp       = (const float*)d_in[24];
    const float* out_w    = (const float*)d_in[25];
    const float* fc1_w    = (const float*)d_in[26];
    const float* fc2_w    = (const float*)d_in[27];

    float *xred, *p, *hv, *featloc, *featglob, *xn, *xz, *ysum;
    cudaGetSymbolAddress((void**)&xred, g_xred);
    cudaGetSymbolAddress((void**)&p, g_p);
    cudaGetSymbolAddress((void**)&hv, g_hv);
    cudaGetSymbolAddress((void**)&featloc, g_featloc);
    cudaGetSymbolAddress((void**)&featglob, g_featglob);
    cudaGetSymbolAddress((void**)&xn, g_xn);
    cudaGetSymbolAddress((void**)&xz, g_xz);
    cudaGetSymbolAddress((void**)&ysum, g_ysum);

    // 0) one-time weight prep
    init_misc_k<<<96, 256>>>(dt_w, xproj_w);
    // 1) x = relu(bn0(reduce_w @ xin))
    gemm128<1, false><<<dim3(36, 2, BB), 256>>>(reduce_w, x, xred, 256, 2304, 512,
        0, (long long)CIN * HWW, (long long)CC * HWW, bn0_g, bn0_b, (const float*)0, 0);
    // 2,3) layernorm over C
    ln_stats_k<<<dim3((HWW + 255) / 256, BB), 256>>>(xred);
    trans_norm_k<<<dim3(HWW / 32, CC / 32, BB), dim3(32, 8)>>>(xred, ln_g, ln_b);
    // 4) in_proj: xz = xn @ in_w.T
    gemm_nt_big<<<dim3(8, 18, BB), 256>>>(xn, in_w, xz, 2304, 1024, 256,
        (long long)LL * CC, (long long)LL * 1024);
    // 5) causal conv1d + silu -> scan-ordered xm
    conv1d_k<<<dim3(LL / CCT, BB, 4), 512>>>(conv_w, conv_b);
    // 6) xproj per (dir,b), permuted weights -> B/C interleaved output
    gemm_xproj<<<dim3(18, 8), 192>>>();
    // 7) dt = softplus(...)
    dt_k<<<dim3(LL / DTT, BB, 4), 512>>>(dt_b);
    // 8) selective scan
    scan_k<<<512, 128>>>(A_log, Dp);
    // 9) gather directions + silu(z) gate
    ysum_k<<<(BL * DI + 255) / 256, 256>>>();
    // 10) feat_global = 0.25 * (out_w @ ysum) + x
    gemm128<3, true><<<dim3(36, 2, BB), 256>>>(out_w, ysum, featglob, 256, 2304, 512,
        0, (long long)LL * DI, (long long)CC * HWW, (const float*)0, (const float*)0,
        xred, (long long)CC * HWW);
    // 11) p = relu(bn1(proj_w @ x))
    gemm128<1, false><<<dim3(36, 2, BB), 256>>>(proj_w, xred, p, 256, 2304, 256,
        0, (long long)CC * HWW, (long long)CC * HWW, bn1_g, bn1_b, (const float*)0, 0);
    // 12) depthwise h+v fused
    dwconv_k<<<(BB * CC * HWW + 255) / 256, 256>>>(p, dwh_w, dwv_w,
                                                   bnh_g, bnh_b, bnv_g, bnv_b, hv);
    // 13) feat_local = fus_w @ (h+v) + fus_b
    gemm128<2, false><<<dim3(36, 2, BB), 256>>>(fus_w, hv, featloc, 256, 2304, 256,
        0, (long long)CC * HWW, (long long)CC * HWW, (const float*)0, fus_b, (const float*)0, 0);
    // 14-16) SE head + final combine
    mean_k<<<dim3(CC, BB), 256>>>();
    fc_k<<<BB, 256>>>(fc1_w, fc2_w);
    final_k<<<(BB * CC * HWW + 255) / 256, 256>>>((float*)d_out);
}